// round 13
// baseline (speedup 1.0000x reference)
#include <cuda_runtime.h>
#include <math.h>
#include <stdint.h>

#define L_TOK   2048
#define DMODEL  512
#define DINNER  1024
#define DSTATE  16
#define DTRANK  32
#define INDIM   1024
#define NLAYER  2
#define NCHUNK  32
#define CHUNK   64    /* L_TOK / NCHUNK */
#define NPOOL   32
#define SPLITK  4

// ---------------- scratch (device globals; no allocation) ----------------
__device__ float g_h    [L_TOK * DMODEL];
__device__ float g_hn   [L_TOK * DMODEL];
__device__ float g_xz   [L_TOK * 2 * DINNER];
__device__ float g_u    [L_TOK * DINNER];
__device__ float g_delta[L_TOK * DINNER];
__device__ float g_y    [L_TOK * DINNER];
__device__ float g_y0   [L_TOK * DINNER];
__device__ float g_ec   [L_TOK * DINNER];
__device__ float g_P    [NCHUNK * DINNER * DSTATE];
__device__ float g_S    [NCHUNK * DINNER * DSTATE];
__device__ float g_init [NCHUNK * DINNER * DSTATE];
__device__ float g_scores[L_TOK];
__device__ float g_rnorm[L_TOK];
__device__ float g_stats[2];
__device__ float g_pool [NPOOL * DMODEL];
__device__ float g_part [SPLITK * L_TOK * 128];

enum { EPI_NONE = 0, EPI_GELU_POS = 1, EPI_SOFTPLUS = 2, EPI_ADD = 3 };

// =========================================================================
// BF16 tensor-core GEMM with ldmatrix (256 threads — R11 proven config).
// Block 128(M) x BN(N), BK=16, 8 warps (4m x 2n), m16n8k16, double-buffered.
// smem rows: 16 bf16 k-order, stride 48 B (conflict-free ldmatrix).
// ASCALE: A-load applies ascale[row]*aw[k] (fused RMSNorm).
// =========================================================================
__device__ __forceinline__ uint32_t packbf(float lo, float hi) {
    uint32_t r;
    asm("cvt.rn.bf16x2.f32 %0, %1, %2;" : "=r"(r) : "f"(hi), "f"(lo));
    return r;
}

__device__ __forceinline__ void mma_bf16(float* d,
                                         uint32_t a0, uint32_t a1, uint32_t a2, uint32_t a3,
                                         uint32_t b0, uint32_t b1)
{
    asm volatile(
        "mma.sync.aligned.m16n8k16.row.col.f32.bf16.bf16.f32 "
        "{%0,%1,%2,%3},{%4,%5,%6,%7},{%8,%9},{%0,%1,%2,%3};"
        : "+f"(d[0]), "+f"(d[1]), "+f"(d[2]), "+f"(d[3])
        : "r"(a0), "r"(a1), "r"(a2), "r"(a3), "r"(b0), "r"(b1));
}

__device__ __forceinline__ void ldsm4(uint32_t& r0, uint32_t& r1,
                                      uint32_t& r2, uint32_t& r3, uint32_t addr)
{
    asm volatile("ldmatrix.sync.aligned.m8n8.x4.shared.b16 {%0,%1,%2,%3}, [%4];"
                 : "=r"(r0), "=r"(r1), "=r"(r2), "=r"(r3) : "r"(addr));
}

#define RSW 12   /* u32 per smem row: 8 data + 4 pad = 48 bytes */

template <int EPI, int BN, int ASCALE>
__global__ __launch_bounds__(256)
void gemm_bf(int M, int N, int K,
             const float* __restrict__ A, int lda,
             const float* __restrict__ B, int ldb,
             float* __restrict__ C, int ldc,
             const float* __restrict__ bias,
             const float* __restrict__ pos,
             const float* __restrict__ pos_w,
             const float* __restrict__ pos_b,
             const float* __restrict__ ascale,
             const float* __restrict__ aw)
{
    constexpr int NTN = BN / 16;
    constexpr int SZA = 128 * RSW;
    constexpr int SZB = BN * RSW;
    __shared__ __align__(16) uint32_t sA[2][SZA];
    __shared__ __align__(16) uint32_t sB[2][SZB];

    const int t   = threadIdx.x;
    const int l   = t & 31;
    const int wid = t >> 5;
    const int wm  = wid >> 1;
    const int wn  = wid & 1;
    const int bm  = blockIdx.y << 7;
    const int bn  = blockIdx.x * BN;

    const int am = t >> 1;
    const int ah = t & 1;
    const float* Asrc = A + (size_t)(bm + am) * lda + ah * 8;
    const float rsc = ASCALE ? ascale[bm + am] : 1.f;

    const int bn0 = t & (BN - 1);
    const int bkq = t / BN;
    constexpr int BKR = (BN == 128) ? 8 : 4;
    const float* Bsrc = B + (size_t)(BKR * bkq) * ldb + bn + bn0;

    const uint32_t aSh = (uint32_t)__cvta_generic_to_shared(&sA[0][0]);
    const uint32_t bSh = (uint32_t)__cvta_generic_to_shared(&sB[0][0]);

    const uint32_t aFrag = (uint32_t)((wm * 32 + (l & 15)) * 48 + (l >> 4) * 16);
    const uint32_t bFrag = (uint32_t)((wn * (BN / 2) + (l & 7) + ((l >> 4) << 3)) * 48
                                      + ((l >> 3) & 1) * 16);

    float acc[2][NTN][4];
#pragma unroll
    for (int i = 0; i < 2; i++)
#pragma unroll
        for (int j = 0; j < NTN; j++)
#pragma unroll
            for (int k = 0; k < 4; k++) acc[i][j][k] = 0.f;

    float4 va0, va1;
    float  vb[8];

    auto loadA = [&](int k0) {
        va0 = *reinterpret_cast<const float4*>(Asrc + k0);
        va1 = *reinterpret_cast<const float4*>(Asrc + k0 + 4);
        if (ASCALE) {
            float4 w0 = *reinterpret_cast<const float4*>(&aw[k0 + ah * 8]);
            float4 w1 = *reinterpret_cast<const float4*>(&aw[k0 + ah * 8 + 4]);
            va0.x *= rsc * w0.x; va0.y *= rsc * w0.y;
            va0.z *= rsc * w0.z; va0.w *= rsc * w0.w;
            va1.x *= rsc * w1.x; va1.y *= rsc * w1.y;
            va1.z *= rsc * w1.z; va1.w *= rsc * w1.w;
        }
    };
    auto loadB = [&](int k0) {
#pragma unroll
        for (int j = 0; j < BKR; j++)
            vb[j] = Bsrc[(size_t)(k0 + j) * ldb];
    };
    auto storeA = [&](int nb) {
        uint4 w = make_uint4(packbf(va0.x, va0.y), packbf(va0.z, va0.w),
                             packbf(va1.x, va1.y), packbf(va1.z, va1.w));
        *reinterpret_cast<uint4*>(&sA[nb][am * RSW + ah * 4]) = w;
    };
    auto storeB = [&](int nb) {
        if (BN == 128) {
            uint4 w = make_uint4(packbf(vb[0], vb[1]), packbf(vb[2], vb[3]),
                                 packbf(vb[4], vb[5]), packbf(vb[6], vb[7]));
            *reinterpret_cast<uint4*>(&sB[nb][bn0 * RSW + bkq * 4]) = w;
        } else {
            uint2 w = make_uint2(packbf(vb[0], vb[1]), packbf(vb[2], vb[3]));
            *reinterpret_cast<uint2*>(&sB[nb][bn0 * RSW + bkq * 2]) = w;
        }
    };

    loadA(0);
    loadB(0);
    storeA(0);
    storeB(0);
    __syncthreads();

    const int NT = K >> 4;
    for (int kt = 0; kt < NT; kt++) {
        if (kt + 1 < NT) {
            const int k0 = (kt + 1) << 4;
            loadA(k0);
            loadB(k0);
        }
        const int buf = kt & 1;
        {
            const uint32_t aBuf = aSh + (uint32_t)buf * (SZA * 4) + aFrag;
            const uint32_t bBuf = bSh + (uint32_t)buf * (SZB * 4) + bFrag;
            uint32_t af[2][4];
#pragma unroll
            for (int mt = 0; mt < 2; mt++)
                ldsm4(af[mt][0], af[mt][1], af[mt][2], af[mt][3],
                      aBuf + (uint32_t)(mt * 16 * 48));
            uint32_t bfm[NTN][2];
#pragma unroll
            for (int ntp = 0; ntp < NTN / 2; ntp++)
                ldsm4(bfm[2 * ntp][0], bfm[2 * ntp][1],
                      bfm[2 * ntp + 1][0], bfm[2 * ntp + 1][1],
                      bBuf + (uint32_t)(ntp * 16 * 48));
#pragma unroll
            for (int nt = 0; nt < NTN; nt++)
#pragma unroll
                for (int mt = 0; mt < 2; mt++)
                    mma_bf16(acc[mt][nt],
                             af[mt][0], af[mt][1], af[mt][2], af[mt][3],
                             bfm[nt][0], bfm[nt][1]);
        }
        if (kt + 1 < NT) {
            const int nb = (kt + 1) & 1;
            storeA(nb);
            storeB(nb);
        }
        __syncthreads();
    }

#pragma unroll
    for (int mt = 0; mt < 2; mt++) {
#pragma unroll
        for (int half = 0; half < 2; half++) {
            const int gm = bm + wm * 32 + mt * 16 + (l >> 2) + half * 8;
            float p0 = 0.f, p1 = 0.f;
            if (EPI == EPI_GELU_POS) { p0 = pos[2 * gm]; p1 = pos[2 * gm + 1]; }
#pragma unroll
            for (int nt = 0; nt < NTN; nt++) {
                const int gn = bn + wn * (BN / 2) + nt * 8 + 2 * (l & 3);
                float v0 = acc[mt][nt][2 * half + 0];
                float v1 = acc[mt][nt][2 * half + 1];
                float* cp = C + (size_t)gm * ldc + gn;
                if (EPI == EPI_GELU_POS) {
                    v0 += bias[gn];
                    v1 += bias[gn + 1];
                    v0 = 0.5f * v0 * (1.f + erff(v0 * 0.70710678118654752f));
                    v1 = 0.5f * v1 * (1.f + erff(v1 * 0.70710678118654752f));
                    v0 += p0 * pos_w[gn]     + p1 * pos_w[DMODEL + gn]     + pos_b[gn];
                    v1 += p0 * pos_w[gn + 1] + p1 * pos_w[DMODEL + gn + 1] + pos_b[gn + 1];
                } else if (EPI == EPI_ADD) {
                    float2 old = *reinterpret_cast<const float2*>(cp);
                    v0 += old.x;
                    v1 += old.y;
                }
                *reinterpret_cast<float2*>(cp) = make_float2(v0, v1);
            }
        }
    }
}

// =========================================================================
// TF32 tensor-core GEMM (unchanged from R11). Block 128x64, m16n8k8.
// =========================================================================
__device__ __forceinline__ uint32_t f2tf(float f) {
    uint32_t u;
    asm("cvt.rna.tf32.f32 %0, %1;" : "=r"(u) : "f"(f));
    return u;
}

__device__ __forceinline__ void mma_tf32(float* d,
                                         uint32_t a0, uint32_t a1, uint32_t a2, uint32_t a3,
                                         uint32_t b0, uint32_t b1)
{
    asm volatile(
        "mma.sync.aligned.m16n8k8.row.col.f32.tf32.tf32.f32 "
        "{%0,%1,%2,%3},{%4,%5,%6,%7},{%8,%9},{%0,%1,%2,%3};"
        : "+f"(d[0]), "+f"(d[1]), "+f"(d[2]), "+f"(d[3])
        : "r"(a0), "r"(a1), "r"(a2), "r"(a3), "r"(b0), "r"(b1));
}

#define RSA 28
#define RSB 28

template <int EPI, int SPLIT, int REDA>
__global__ __launch_bounds__(256)
void gemm_tc(int M, int N, int K, int Nreal,
             const float* __restrict__ A, int lda,
             const float* __restrict__ B, int ldb,
             float* __restrict__ C, int ldc,
             const float* __restrict__ bias)
{
    __shared__ __align__(16) uint32_t sA[2][128 * RSA];
    __shared__ __align__(16) uint32_t sB[2][64 * RSB];

    const int t   = threadIdx.x;
    const int l   = t & 31;
    const int wid = t >> 5;
    const int wm  = wid >> 1;
    const int wn  = wid & 1;
    const int bm  = blockIdx.y << 7;
    const int bn  = blockIdx.x << 6;

    int kOff = 0, KS = K;
    if (SPLIT > 0) {
        KS   = K / SPLIT;
        kOff = blockIdx.z * KS;
        C   += (size_t)blockIdx.z * M * N;
    }

    const int am = t >> 1;
    const int ah = t & 1;
    const float* Asrc = A + (size_t)(bm + am) * lda + kOff + ah * 8;
    const int bkq = t >> 6;
    const int bn0 = t & 63;
    const bool bok = (bn + bn0) < Nreal;
    const int bcol = bok ? (bn + bn0) : 0;
    const float* Bsrc = B + (size_t)(kOff + bkq) * ldb + bcol;

    float acc[2][4][4];
#pragma unroll
    for (int i = 0; i < 2; i++)
#pragma unroll
        for (int j = 0; j < 4; j++)
#pragma unroll
            for (int k = 0; k < 4; k++) acc[i][j][k] = 0.f;

    float4 va0, va1;
    float  vb0, vb1, vb2, vb3;

    auto loadA = [&](int k0) {
        va0 = *reinterpret_cast<const float4*>(Asrc + k0);
        va1 = *reinterpret_cast<const float4*>(Asrc + k0 + 4);
        if (REDA) {
#pragma unroll
            for (int z = 1; z < SPLITK; z++) {
                const float* s = Asrc + (size_t)z * L_TOK * 128 + k0;
                float4 e0 = *reinterpret_cast<const float4*>(s);
                float4 e1 = *reinterpret_cast<const float4*>(s + 4);
                va0.x += e0.x; va0.y += e0.y; va0.z += e0.z; va0.w += e0.w;
                va1.x += e1.x; va1.y += e1.y; va1.z += e1.z; va1.w += e1.w;
            }
        }
    };
    auto loadB = [&](int k0) {
        if (bok) {
            const float* bs = Bsrc + (size_t)k0 * ldb;
            vb0 = bs[0];
            vb1 = bs[(size_t)4 * ldb];
            vb2 = bs[(size_t)8 * ldb];
            vb3 = bs[(size_t)12 * ldb];
        } else {
            vb0 = vb1 = vb2 = vb3 = 0.f;
        }
    };
    auto storeAB = [&](int nb) {
        uint4 w0 = make_uint4(f2tf(va0.x), f2tf(va1.x), f2tf(va0.y), f2tf(va1.y));
        uint4 w1 = make_uint4(f2tf(va0.z), f2tf(va1.z), f2tf(va0.w), f2tf(va1.w));
        *reinterpret_cast<uint4*>(&sA[nb][am * RSA + ah * 8])     = w0;
        *reinterpret_cast<uint4*>(&sA[nb][am * RSA + ah * 8 + 4]) = w1;
        *reinterpret_cast<uint2*>(&sB[nb][bn0 * RSB + 2 * bkq])     = make_uint2(f2tf(vb0), f2tf(vb1));
        *reinterpret_cast<uint2*>(&sB[nb][bn0 * RSB + 8 + 2 * bkq]) = make_uint2(f2tf(vb2), f2tf(vb3));
    };

    loadA(0);
    loadB(0);
    storeAB(0);
    __syncthreads();

    const int NT = KS >> 4;
    for (int kt = 0; kt < NT; kt++) {
        if (kt + 1 < NT) {
            const int k0 = (kt + 1) << 4;
            loadA(k0);
            loadB(k0);
        }
        const int buf = kt & 1;
#pragma unroll
        for (int ks = 0; ks < 2; ks++) {
            uint32_t af[2][4];
#pragma unroll
            for (int mt = 0; mt < 2; mt++) {
                const int r = wm * 32 + mt * 16 + (l >> 2);
                uint2 lo = *reinterpret_cast<const uint2*>(&sA[buf][r * RSA + ks * 8 + 2 * (l & 3)]);
                uint2 hi = *reinterpret_cast<const uint2*>(&sA[buf][(r + 8) * RSA + ks * 8 + 2 * (l & 3)]);
                af[mt][0] = lo.x; af[mt][1] = hi.x; af[mt][2] = lo.y; af[mt][3] = hi.y;
            }
#pragma unroll
            for (int nt = 0; nt < 4; nt++) {
                const int n = wn * 32 + nt * 8 + (l >> 2);
                uint2 bf = *reinterpret_cast<const uint2*>(&sB[buf][n * RSB + ks * 8 + 2 * (l & 3)]);
#pragma unroll
                for (int mt = 0; mt < 2; mt++)
                    mma_tf32(acc[mt][nt],
                             af[mt][0], af[mt][1], af[mt][2], af[mt][3], bf.x, bf.y);
            }
        }
        if (kt + 1 < NT) {
            storeAB((kt + 1) & 1);
        }
        __syncthreads();
    }

#pragma unroll
    for (int mt = 0; mt < 2; mt++) {
#pragma unroll
        for (int half = 0; half < 2; half++) {
            const int gm = bm + wm * 32 + mt * 16 + (l >> 2) + half * 8;
#pragma unroll
            for (int nt = 0; nt < 4; nt++) {
                const int gn = bn + wn * 32 + nt * 8 + 2 * (l & 3);
                float v0 = acc[mt][nt][2 * half + 0];
                float v1 = acc[mt][nt][2 * half + 1];
                float* cp = C + (size_t)gm * ldc + gn;
                if (EPI == EPI_SOFTPLUS) {
                    v0 += bias[gn];
                    v1 += bias[gn + 1];
                    v0 = (v0 > 15.f) ? v0 : log1pf(expf(v0));
                    v1 = (v1 > 15.f) ? v1 : log1pf(expf(v1));
                }
                *reinterpret_cast<float2*>(cp) = make_float2(v0, v1);
            }
        }
    }
}

// ---------------- attn reduce ----------------
__global__ __launch_bounds__(128)
void attn_score_kernel(const float* __restrict__ part,
                       const float* __restrict__ b1,
                       const float* __restrict__ w2,
                       const float* __restrict__ b2,
                       float* __restrict__ scores)
{
    __shared__ float red[128];
    int row = blockIdx.x;
    int d   = threadIdx.x;
    size_t off = (size_t)row * 128 + d;
    float v = part[off];
#pragma unroll
    for (int z = 1; z < SPLITK; z++)
        v += part[(size_t)z * L_TOK * 128 + off];
    float s = tanhf(v + b1[d]) * w2[d];
    red[d] = s;
    __syncthreads();
    for (int st = 64; st > 0; st >>= 1) {
        if (d < st) red[d] += red[d + st];
        __syncthreads();
    }
    if (d == 0) scores[row] = red[0] + b2[0];
}

// ---------------- per-row RMS scale ----------------
__global__ __launch_bounds__(256)
void rownorm_kernel(const float* __restrict__ h, float* __restrict__ rn)
{
    int w = threadIdx.x >> 5;
    int l = threadIdx.x & 31;
    int row = blockIdx.x * 8 + w;
    const float* r = h + (size_t)row * DMODEL;
    float ss = 0.f;
#pragma unroll
    for (int i = 0; i < DMODEL / 32; i++) {
        float v = r[l + i * 32];
        ss = fmaf(v, v, ss);
    }
#pragma unroll
    for (int o = 16; o > 0; o >>= 1) ss += __shfl_down_sync(0xffffffff, ss, o);
    if (l == 0) rn[row] = rsqrtf(ss * (1.f / DMODEL) + 1e-5f);
}

// ---------------- block reduce helper ----------------
__device__ __forceinline__ float block_reduce_sum(float v, float* sred)
{
    int tid = threadIdx.x;
#pragma unroll
    for (int o = 16; o > 0; o >>= 1) v += __shfl_down_sync(0xffffffff, v, o);
    if ((tid & 31) == 0) sred[tid >> 5] = v;
    __syncthreads();
    float r;
    if (tid < 32) {
        int nw = blockDim.x >> 5;
        r = (tid < nw) ? sred[tid] : 0.f;
#pragma unroll
        for (int o = 16; o > 0; o >>= 1) r += __shfl_down_sync(0xffffffff, r, o);
        if (tid == 0) sred[0] = r;
    }
    __syncthreads();
    r = sred[0];
    __syncthreads();
    return r;
}

// ---------------- LayerNorm ----------------
__global__ void layernorm_kernel(const float* __restrict__ h,
                                 const float* __restrict__ w,
                                 const float* __restrict__ b,
                                 float* __restrict__ out)
{
    __shared__ float sred[32];
    int t = blockIdx.x;
    const float* row = h + (size_t)t * DMODEL;
    float s = 0.f, ss = 0.f;
    for (int d = threadIdx.x; d < DMODEL; d += blockDim.x) {
        float v = row[d];
        s += v;
        ss = fmaf(v, v, ss);
    }
    float tot  = block_reduce_sum(s, sred);
    float tot2 = block_reduce_sum(ss, sred);
    float mu  = tot * (1.f / DMODEL);
    float var = tot2 * (1.f / DMODEL) - mu * mu;
    float sc  = rsqrtf(var + 1e-5f);
    for (int d = threadIdx.x; d < DMODEL; d += blockDim.x)
        out[(size_t)t * DMODEL + d] = (row[d] - mu) * sc * w[d] + b[d];
}

// ---------------- depthwise causal conv1d + SiLU (scalar, R11) ------------
__global__ void conv_silu_kernel(const float* __restrict__ xz,
                                 const float* __restrict__ cw,
                                 const float* __restrict__ cb,
                                 float* __restrict__ u)
{
    int idx = blockIdx.x * blockDim.x + threadIdx.x;
    if (idx >= L_TOK * DINNER) return;
    int t = idx >> 10, c = idx & 1023;
    const float* w = cw + c * 4;
    float acc = cb[c];
#pragma unroll
    for (int k = 0; k < 4; k++) {
        int tt = t - 3 + k;
        if (tt >= 0) acc = fmaf(w[k], xz[(size_t)tt * (2 * DINNER) + c], acc);
    }
    u[idx] = acc / (1.f + __expf(-acc));
}

// ---------------- scan pass A: chunk states + y0/Ecum (fast path) ---------
__global__ __launch_bounds__(128)
void scan_a_kernel(const float* __restrict__ delta,
                   const float* __restrict__ u,
                   const float* __restrict__ part,
                   const float* __restrict__ A_log,
                   const float* __restrict__ Dd,
                   float* __restrict__ Pout,
                   float* __restrict__ Sout,
                   float* __restrict__ y0,
                   float* __restrict__ ec)
{
    __shared__ float sB[CHUNK][DSTATE];
    __shared__ float sC[CHUNK][DSTATE];
    int e  = blockIdx.y * 128 + threadIdx.x;
    int c  = blockIdx.x;
    int t0 = c * CHUNK;
    for (int i = threadIdx.x; i < CHUNK * DSTATE; i += 128) {
        int tl = i >> 4, n = i & 15;
        size_t offB = (size_t)(t0 + tl) * 128 + 32 + n;
        size_t offC = (size_t)(t0 + tl) * 128 + 48 + n;
        float sb = part[offB];
        float sc2 = part[offC];
#pragma unroll
        for (int z = 1; z < SPLITK; z++) {
            sb  += part[(size_t)z * L_TOK * 128 + offB];
            sc2 += part[(size_t)z * L_TOK * 128 + offC];
        }
        sB[tl][n] = sb;
        sC[tl][n] = sc2;
    }
    float Aneg[DSTATE], h[DSTATE];
    bool fast = true;
#pragma unroll
    for (int n = 0; n < DSTATE; n++) {
        Aneg[n] = -expf(A_log[(size_t)e * DSTATE + n]);
        fast = fast && (fabsf(Aneg[n] + (float)(n + 1)) < 1e-3f * (n + 1));
        h[n] = 0.f;
    }
    int bfast = __syncthreads_and(fast ? 1 : 0);   // also covers smem staging
    size_t base = ((size_t)c * DINNER + e) * DSTATE;
    float Dde = Dd[e];
    if (bfast) {
        float ecr = 1.f;
        for (int tl = 0; tl < CHUNK; tl++) {
            int   t  = t0 + tl;
            float dl = delta[(size_t)t * DINNER + e];
            float ul = u[(size_t)t * DINNER + e];
            float du = dl * ul;
            float E  = __expf(-dl);
            ecr *= E;
            float pw = 1.f;
            float acc = Dde * ul;
#pragma unroll
            for (int n = 0; n < DSTATE; n++) {
                pw *= E;
                h[n] = fmaf(pw, h[n], du * sB[tl][n]);
                acc  = fmaf(h[n], sC[tl][n], acc);
            }
            y0[(size_t)t * DINNER + e] = acc;
            ec[(size_t)t * DINNER + e] = ecr;
        }
        float pp = 1.f;
#pragma unroll
        for (int n = 0; n < DSTATE; n++) {
            pp *= ecr;
            Sout[base + n] = h[n];
            Pout[base + n] = pp;
        }
    } else {
        float P[DSTATE];
#pragma unroll
        for (int n = 0; n < DSTATE; n++) P[n] = 1.f;
        for (int tl = 0; tl < CHUNK; tl++) {
            int   t  = t0 + tl;
            float dl = delta[(size_t)t * DINNER + e];
            float ul = u[(size_t)t * DINNER + e];
            float du = dl * ul;
#pragma unroll
            for (int n = 0; n < DSTATE; n++) {
                float dA = __expf(dl * Aneg[n]);
                h[n] = fmaf(dA, h[n], du * sB[tl][n]);
                P[n] *= dA;
            }
        }
#pragma unroll
        for (int n = 0; n < DSTATE; n++) {
            Sout[base + n] = h[n];
            Pout[base + n] = P[n];
        }
    }
}

// ---------------- scan pass B ----------------
__global__ void scan_b_kernel(const float* __restrict__ P,
                              const float* __restrict__ S,
                              float* __restrict__ init)
{
    int e = blockIdx.x * blockDim.x + threadIdx.x;
    if (e >= DINNER) return;
    float h[DSTATE];
#pragma unroll
    for (int n = 0; n < DSTATE; n++) h[n] = 0.f;
    for (int c = 0; c < NCHUNK; c++) {
        size_t base = ((size_t)c * DINNER + e) * DSTATE;
#pragma unroll
        for (int n = 0; n < DSTATE; n++) init[base + n] = h[n];
#pragma unroll
        for (int n = 0; n < DSTATE; n++)
            h[n] = fmaf(P[base + n], h[n], S[base + n]);
    }
}

// ---------------- scan pass C: elementwise correction (fast) or replay ----
__global__ __launch_bounds__(128)
void scan_c_kernel(const float* __restrict__ delta,
                   const float* __restrict__ u,
                   const float* __restrict__ part,
                   const float* __restrict__ A_log,
                   const float* __restrict__ Dd,
                   const float* __restrict__ init,
                   const float* __restrict__ xz,
                   const float* __restrict__ y0,
                   const float* __restrict__ ec,
                   float* __restrict__ y)
{
    __shared__ float sB[CHUNK][DSTATE];
    __shared__ float sC[CHUNK][DSTATE];
    int e  = blockIdx.y * 128 + threadIdx.x;
    int c  = blockIdx.x;
    int t0 = c * CHUNK;
    for (int i = threadIdx.x; i < CHUNK * DSTATE; i += 128) {
        int tl = i >> 4, n = i & 15;
        size_t offB = (size_t)(t0 + tl) * 128 + 32 + n;
        size_t offC = (size_t)(t0 + tl) * 128 + 48 + n;
        float sb = part[offB];
        float sc2 = part[offC];
#pragma unroll
        for (int z = 1; z < SPLITK; z++) {
            sb  += part[(size_t)z * L_TOK * 128 + offB];
            sc2 += part[(size_t)z * L_TOK * 128 + offC];
        }
        sB[tl][n] = sb;
        sC[tl][n] = sc2;
    }
    float Aneg[DSTATE], hv[DSTATE];
    bool fast = true;
    size_t base = ((size_t)c * DINNER + e) * DSTATE;
#pragma unroll
    for (int n = 0; n < DSTATE; n++) {
        Aneg[n] = -expf(A_log[(size_t)e * DSTATE + n]);
        fast = fast && (fabsf(Aneg[n] + (float)(n + 1)) < 1e-3f * (n + 1));
        hv[n]   = init[base + n];
    }
    int bfast = __syncthreads_and(fast ? 1 : 0);
    if (bfast) {
        // y = (y0 + sum_n C*Ecum^(n+1)*init_n) * silu(z) -- no t recurrence
        for (int tl = 0; tl < CHUNK; tl++) {
            int   t  = t0 + tl;
            size_t idx = (size_t)t * DINNER + e;
            float base_y = y0[idx];
            float ecv = ec[idx];
            float pw = 1.f, add = 0.f;
#pragma unroll
            for (int n = 0; n < DSTATE; n++) {
                pw *= ecv;
                add = fmaf(sC[tl][n] * pw, hv[n], add);
            }
            float zv = xz[(size_t)t * (2 * DINNER) + DINNER + e];
            float sz = zv / (1.f + __expf(-zv));
            y[idx] = (base_y + add) * sz;
        }
    } else {
        float Dde = Dd[e];
        for (int tl = 0; tl < CHUNK; tl++) {
            int   t  = t0 + tl;
            float dl = delta[(size_t)t * DINNER + e];
            float ul = u[(size_t)t * DINNER + e];
            float du = dl * ul;
            float acc = Dde * ul;
#pragma unroll
            for (int n = 0; n < DSTATE; n++) {
                float dA = __expf(dl * Aneg[n]);
                hv[n] = fmaf(dA, hv[n], du * sB[tl][n]);
                acc  = fmaf(hv[n], sC[tl][n], acc);
            }
            float zv = xz[(size_t)t * (2 * DINNER) + DINNER + e];
            float sz = zv / (1.f + __expf(-zv));
            y[(size_t)t * DINNER + e] = acc * sz;
        }
    }
}

// ---------------- softmax stats ----------------
__global__ __launch_bounds__(512)
void softmax_stats_kernel(const float* __restrict__ scores,
                          float* __restrict__ stats)
{
    __shared__ float red[512];
    int tid = threadIdx.x;
    float mx = fmaxf(scores[tid], scores[tid + 512]);
    mx = fmaxf(mx, fmaxf(scores[tid + 1024], scores[tid + 1536]));
    red[tid] = mx;
    __syncthreads();
    for (int s = 256; s > 0; s >>= 1) {
        if (tid < s) red[tid] = fmaxf(red[tid], red[tid + s]);
        __syncthreads();
    }
    mx = red[0];
    __syncthreads();
    float lsum = expf(scores[tid] - mx) + expf(scores[tid + 512] - mx)
               + expf(scores[tid + 1024] - mx) + expf(scores[tid + 1536] - mx);
    red[tid] = lsum;
    __syncthreads();
    for (int s = 256; s > 0; s >>= 1) {
        if (tid < s) red[tid] += red[tid + s];
        __syncthreads();
    }
    if (tid == 0) { stats[0] = mx; stats[1] = red[0]; }
}

// ---------------- pooling partials ----------------
__global__ __launch_bounds__(512)
void pool_partial_kernel(const float* __restrict__ hn,
                         const float* __restrict__ scores,
                         const float* __restrict__ stats,
                         float* __restrict__ pool)
{
    int tid = threadIdx.x;
    int b   = blockIdx.x;
    float mx = stats[0];
    float acc = 0.f;
    int t0 = b * (L_TOK / NPOOL);
    for (int i = 0; i < L_TOK / NPOOL; i++) {
        int t = t0 + i;
        float w = __expf(scores[t] - mx);
        acc = fmaf(w, hn[(size_t)t * DMODEL + tid], acc);
    }
    pool[(size_t)b * DMODEL + tid] = acc;
}

// ---------------- final reduce + classifier ----------------
__global__ __launch_bounds__(512)
void pool_final_kernel(const float* __restrict__ pool,
                       const float* __restrict__ stats,
                       const float* __restrict__ cls_w,
                       const float* __restrict__ cls_b,
                       float* __restrict__ out)
{
    __shared__ float red[512];
    int tid = threadIdx.x;
    float acc = 0.f;
#pragma unroll
    for (int b = 0; b < NPOOL; b++)
        acc += pool[(size_t)b * DMODEL + tid];
    acc /= stats[1];
#pragma unroll
    for (int c = 0; c < 2; c++) {
        red[tid] = acc * cls_w[tid * 2 + c];
        __syncthreads();
        for (int s = 256; s > 0; s >>= 1) {
            if (tid < s) red[tid] += red[tid + s];
            __syncthreads();
        }
        if (tid == 0) out[c] = red[0] + cls_b[c];
        __syncthreads();
    }
}

// ---------------- host launcher ----------------
extern "C" void kernel_launch(void* const* d_in, const int* in_sizes, int n_in,
                              void* d_out, int out_size)
{
    const float* x       = (const float*)d_in[0];
    const float* pos     = (const float*)d_in[1];
    const float* fc1_w   = (const float*)d_in[2];
    const float* fc1_b   = (const float*)d_in[3];
    const float* pos_w   = (const float*)d_in[4];
    const float* pos_b   = (const float*)d_in[5];
    const float* in_proj = (const float*)d_in[6];
    const float* conv_w  = (const float*)d_in[7];
    const float* conv_b  = (const float*)d_in[8];
    const float* x_proj  = (const float*)d_in[9];
    const float* dt_w    = (const float*)d_in[10];
    const float* dt_b    = (const float*)d_in[11];
    const float* A_log   = (const float*)d_in[12];
    const float* Dd      = (const float*)d_in[13];
    const float* out_w   = (const float*)d_in[14];
    const float* rms_w   = (const float*)d_in[15];
    const float* norm_w  = (const float*)d_in[16];
    const float* norm_b  = (const float*)d_in[17];
    const float* attn_w1 = (const float*)d_in[18];
    const float* attn_b1 = (const float*)d_in[19];
    const float* attn_w2 = (const float*)d_in[20];
    const float* attn_b2 = (const float*)d_in[21];
    const float* cls_w   = (const float*)d_in[22];
    const float* cls_b   = (const float*)d_in[23];

    float *p_h, *p_hn, *p_xz, *p_u, *p_delta, *p_y, *p_y0, *p_ec;
    float *p_P, *p_S, *p_init, *p_scores, *p_rnorm, *p_stats, *p_pool, *p_part;
    cudaGetSymbolAddress((void**)&p_h,      g_h);
    cudaGetSymbolAddress((void**)&p_hn,     g_hn);
    cudaGetSymbolAddress((void**)&p_xz,     g_xz);
    cudaGetSymbolAddress((void**)&p_u,      g_u);
    cudaGetSymbolAddress((void**)&p_delta,  g_delta);
    cudaGetSymbolAddress((void**)&p_y,      g_y);
    cudaGetSymbolAddress((void**)&p_y0,     g_y0);
    cudaGetSymbolAddress((void**)&p_ec,     g_ec);
    cudaGetSymbolAddress((void**)&p_P,      g_P);
    cudaGetSymbolAddress((void**)&p_S,      g_S);
    cudaGetSymbolAddress((void**)&p_init,   g_init);
    cudaGetSymbolAddress((void**)&p_scores, g_scores);
    cudaGetSymbolAddress((void**)&p_rnorm,  g_rnorm);
    cudaGetSymbolAddress((void**)&p_stats,  g_stats);
    cudaGetSymbolAddress((void**)&p_pool,   g_pool);
    cudaGetSymbolAddress((void**)&p_part,   g_part);

    // fc1 + GELU + pos (bf16)
    gemm_bf<EPI_GELU_POS, 64, 0><<<dim3(DMODEL / 64, L_TOK / 128), 256>>>(
        L_TOK, DMODEL, INDIM, x, INDIM, fc1_w, DMODEL, p_h, DMODEL,
        fc1_b, pos, pos_w, pos_b, nullptr, nullptr);

    for (int l = 0; l < NLAYER; l++) {
        rownorm_kernel<<<L_TOK / 8, 256>>>(p_h, p_rnorm);

        gemm_bf<EPI_NONE, 128, 1><<<dim3(2 * DINNER / 128, L_TOK / 128), 256>>>(
            L_TOK, 2 * DINNER, DMODEL,
            p_h, DMODEL,
            in_proj + (size_t)l * DMODEL * 2 * DINNER, 2 * DINNER,
            p_xz, 2 * DINNER, nullptr, nullptr, nullptr, nullptr,
            p_rnorm, rms_w + (size_t)l * DMODEL);

        conv_silu_kernel<<<(L_TOK * DINNER) / 256, 256>>>(
            p_xz, conv_w + (size_t)l * DINNER * 4, conv_b + (size_t)l * DINNER, p_u);

        gemm_tc<EPI_NONE, SPLITK, 0><<<dim3(2, L_TOK / 128, SPLITK), 256>>>(
            L_TOK, 128, DINNER, 80,
            p_u, DINNER,
            x_proj + (size_t)l * DINNER * 80, 80,
            p_part, 128, nullptr);

        gemm_tc<EPI_SOFTPLUS, 0, 1><<<dim3(DINNER / 64, L_TOK / 128), 256>>>(
            L_TOK, DINNER, DTRANK, DINNER,
            p_part, 128,
            dt_w + (size_t)l * DTRANK * DINNER, DINNER,
            p_delta, DINNER, dt_b + (size_t)l * DINNER);

        scan_a_kernel<<<dim3(NCHUNK, DINNER / 128), 128>>>(
            p_delta, p_u, p_part, A_log + (size_t)l * DINNER * DSTATE,
            Dd + (size_t)l * DINNER, p_P, p_S, p_y0, p_ec);
        scan_b_kernel<<<DINNER / 256, 256>>>(p_P, p_S, p_init);
        scan_c_kernel<<<dim3(NCHUNK, DINNER / 128), 128>>>(
            p_delta, p_u, p_part, A_log + (size_t)l * DINNER * DSTATE,
            Dd + (size_t)l * DINNER, p_init, p_xz, p_y0, p_ec, p_y);

        gemm_bf<EPI_ADD, 64, 0><<<dim3(DMODEL / 64, L_TOK / 128), 256>>>(
            L_TOK, DMODEL, DINNER,
            p_y, DINNER,
            out_w + (size_t)l * DINNER * DMODEL, DMODEL,
            p_h, DMODEL, nullptr, nullptr, nullptr, nullptr, nullptr, nullptr);
    }

    layernorm_kernel<<<L_TOK, 256>>>(p_h, norm_w, norm_b, p_hn);

    gemm_tc<EPI_NONE, SPLITK, 0><<<dim3(2, L_TOK / 128, SPLITK), 256>>>(
        L_TOK, 128, DMODEL, 128,
        p_hn, DMODEL,
        attn_w1, 128,
        p_part, 128, nullptr);
    attn_score_kernel<<<L_TOK, 128>>>(p_part, attn_b1, attn_w2, attn_b2, p_scores);

    softmax_stats_kernel<<<1, 512>>>(p_scores, p_stats);
    pool_partial_kernel<<<NPOOL, 512>>>(p_hn, p_scores, p_stats, p_pool);
    pool_final_kernel<<<1, 512>>>(p_pool, p_stats, cls_w, cls_b, (float*)d_out);
}

// round 15
// speedup vs baseline: 1.0593x; 1.0593x over previous
#include <cuda_runtime.h>
#include <math.h>
#include <stdint.h>

#define L_TOK   2048
#define DMODEL  512
#define DINNER  1024
#define DSTATE  16
#define DTRANK  32
#define INDIM   1024
#define NLAYER  2
#define NCHUNK  32
#define CHUNK   64    /* L_TOK / NCHUNK */
#define NPOOL   32
#define SPLITK  4

// ---------------- scratch (device globals; no allocation) ----------------
__device__ float g_h    [L_TOK * DMODEL];
__device__ float g_hn   [L_TOK * DMODEL];
__device__ float g_xz   [L_TOK * 2 * DINNER];
__device__ float g_u    [L_TOK * DINNER];
__device__ float g_delta[L_TOK * DINNER];
__device__ float g_y    [L_TOK * DINNER];
__device__ float g_P    [NCHUNK * DINNER * DSTATE];
__device__ float g_S    [NCHUNK * DINNER * DSTATE];
__device__ float g_init [NCHUNK * DINNER * DSTATE];
__device__ float g_scores[L_TOK];
__device__ float g_rnorm[L_TOK];
__device__ float g_stats[2];
__device__ float g_pool [NPOOL * DMODEL];
__device__ float g_part [SPLITK * L_TOK * 128];

enum { EPI_NONE = 0, EPI_GELU_POS = 1, EPI_SOFTPLUS = 2, EPI_ADD = 3 };

// =========================================================================
// BF16 tensor-core GEMM with ldmatrix fragment loads (R11 champion config).
// Block 128(M) x BN(N), BK=16, 256 thr, 8 warps (4m x 2n), m16n8k16,
// double-buffered. smem rows: 16 bf16 k-order, row stride 48 B (conflict-free
// on all 4 ldmatrix phases). ASCALE: A-load applies ascale[row]*aw[k]
// (fused RMSNorm).
// =========================================================================
__device__ __forceinline__ uint32_t packbf(float lo, float hi) {
    uint32_t r;
    asm("cvt.rn.bf16x2.f32 %0, %1, %2;" : "=r"(r) : "f"(hi), "f"(lo));
    return r;
}

__device__ __forceinline__ void mma_bf16(float* d,
                                         uint32_t a0, uint32_t a1, uint32_t a2, uint32_t a3,
                                         uint32_t b0, uint32_t b1)
{
    asm volatile(
        "mma.sync.aligned.m16n8k16.row.col.f32.bf16.bf16.f32 "
        "{%0,%1,%2,%3},{%4,%5,%6,%7},{%8,%9},{%0,%1,%2,%3};"
        : "+f"(d[0]), "+f"(d[1]), "+f"(d[2]), "+f"(d[3])
        : "r"(a0), "r"(a1), "r"(a2), "r"(a3), "r"(b0), "r"(b1));
}

__device__ __forceinline__ void ldsm4(uint32_t& r0, uint32_t& r1,
                                      uint32_t& r2, uint32_t& r3, uint32_t addr)
{
    asm volatile("ldmatrix.sync.aligned.m8n8.x4.shared.b16 {%0,%1,%2,%3}, [%4];"
                 : "=r"(r0), "=r"(r1), "=r"(r2), "=r"(r3) : "r"(addr));
}

#define RSW 12   /* u32 per smem row: 8 data + 4 pad = 48 bytes */

template <int EPI, int BN, int ASCALE>
__global__ __launch_bounds__(256)
void gemm_bf(int M, int N, int K,
             const float* __restrict__ A, int lda,
             const float* __restrict__ B, int ldb,
             float* __restrict__ C, int ldc,
             const float* __restrict__ bias,
             const float* __restrict__ pos,
             const float* __restrict__ pos_w,
             const float* __restrict__ pos_b,
             const float* __restrict__ ascale,
             const float* __restrict__ aw)
{
    constexpr int NTN = BN / 16;
    constexpr int SZA = 128 * RSW;
    constexpr int SZB = BN * RSW;
    __shared__ __align__(16) uint32_t sA[2][SZA];
    __shared__ __align__(16) uint32_t sB[2][SZB];

    const int t   = threadIdx.x;
    const int l   = t & 31;
    const int wid = t >> 5;
    const int wm  = wid >> 1;
    const int wn  = wid & 1;
    const int bm  = blockIdx.y << 7;
    const int bn  = blockIdx.x * BN;

    const int am = t >> 1;
    const int ah = t & 1;
    const float* Asrc = A + (size_t)(bm + am) * lda + ah * 8;
    const float rsc = ASCALE ? ascale[bm + am] : 1.f;

    const int bn0 = t & (BN - 1);
    const int bkq = t / BN;
    constexpr int BKR = (BN == 128) ? 8 : 4;
    const float* Bsrc = B + (size_t)(BKR * bkq) * ldb + bn + bn0;

    const uint32_t aSh = (uint32_t)__cvta_generic_to_shared(&sA[0][0]);
    const uint32_t bSh = (uint32_t)__cvta_generic_to_shared(&sB[0][0]);

    const uint32_t aFrag = (uint32_t)((wm * 32 + (l & 15)) * 48 + (l >> 4) * 16);
    const uint32_t bFrag = (uint32_t)((wn * (BN / 2) + (l & 7) + ((l >> 4) << 3)) * 48
                                      + ((l >> 3) & 1) * 16);

    float acc[2][NTN][4];
#pragma unroll
    for (int i = 0; i < 2; i++)
#pragma unroll
        for (int j = 0; j < NTN; j++)
#pragma unroll
            for (int k = 0; k < 4; k++) acc[i][j][k] = 0.f;

    float4 va0, va1;
    float  vb[8];

    auto loadA = [&](int k0) {
        va0 = *reinterpret_cast<const float4*>(Asrc + k0);
        va1 = *reinterpret_cast<const float4*>(Asrc + k0 + 4);
        if (ASCALE) {
            float4 w0 = *reinterpret_cast<const float4*>(&aw[k0 + ah * 8]);
            float4 w1 = *reinterpret_cast<const float4*>(&aw[k0 + ah * 8 + 4]);
            va0.x *= rsc * w0.x; va0.y *= rsc * w0.y;
            va0.z *= rsc * w0.z; va0.w *= rsc * w0.w;
            va1.x *= rsc * w1.x; va1.y *= rsc * w1.y;
            va1.z *= rsc * w1.z; va1.w *= rsc * w1.w;
        }
    };
    auto loadB = [&](int k0) {
#pragma unroll
        for (int j = 0; j < BKR; j++)
            vb[j] = Bsrc[(size_t)(k0 + j) * ldb];
    };
    auto storeA = [&](int nb) {
        uint4 w = make_uint4(packbf(va0.x, va0.y), packbf(va0.z, va0.w),
                             packbf(va1.x, va1.y), packbf(va1.z, va1.w));
        *reinterpret_cast<uint4*>(&sA[nb][am * RSW + ah * 4]) = w;
    };
    auto storeB = [&](int nb) {
        if (BN == 128) {
            uint4 w = make_uint4(packbf(vb[0], vb[1]), packbf(vb[2], vb[3]),
                                 packbf(vb[4], vb[5]), packbf(vb[6], vb[7]));
            *reinterpret_cast<uint4*>(&sB[nb][bn0 * RSW + bkq * 4]) = w;
        } else {
            uint2 w = make_uint2(packbf(vb[0], vb[1]), packbf(vb[2], vb[3]));
            *reinterpret_cast<uint2*>(&sB[nb][bn0 * RSW + bkq * 2]) = w;
        }
    };

    loadA(0);
    loadB(0);
    storeA(0);
    storeB(0);
    __syncthreads();

    const int NT = K >> 4;
    for (int kt = 0; kt < NT; kt++) {
        if (kt + 1 < NT) {
            const int k0 = (kt + 1) << 4;
            loadA(k0);
            loadB(k0);
        }
        const int buf = kt & 1;
        {
            const uint32_t aBuf = aSh + (uint32_t)buf * (SZA * 4) + aFrag;
            const uint32_t bBuf = bSh + (uint32_t)buf * (SZB * 4) + bFrag;
            uint32_t af[2][4];
#pragma unroll
            for (int mt = 0; mt < 2; mt++)
                ldsm4(af[mt][0], af[mt][1], af[mt][2], af[mt][3],
                      aBuf + (uint32_t)(mt * 16 * 48));
            uint32_t bfm[NTN][2];
#pragma unroll
            for (int ntp = 0; ntp < NTN / 2; ntp++)
                ldsm4(bfm[2 * ntp][0], bfm[2 * ntp][1],
                      bfm[2 * ntp + 1][0], bfm[2 * ntp + 1][1],
                      bBuf + (uint32_t)(ntp * 16 * 48));
#pragma unroll
            for (int nt = 0; nt < NTN; nt++)
#pragma unroll
                for (int mt = 0; mt < 2; mt++)
                    mma_bf16(acc[mt][nt],
                             af[mt][0], af[mt][1], af[mt][2], af[mt][3],
                             bfm[nt][0], bfm[nt][1]);
        }
        if (kt + 1 < NT) {
            const int nb = (kt + 1) & 1;
            storeA(nb);
            storeB(nb);
        }
        __syncthreads();
    }

#pragma unroll
    for (int mt = 0; mt < 2; mt++) {
#pragma unroll
        for (int half = 0; half < 2; half++) {
            const int gm = bm + wm * 32 + mt * 16 + (l >> 2) + half * 8;
            float p0 = 0.f, p1 = 0.f;
            if (EPI == EPI_GELU_POS) { p0 = pos[2 * gm]; p1 = pos[2 * gm + 1]; }
#pragma unroll
            for (int nt = 0; nt < NTN; nt++) {
                const int gn = bn + wn * (BN / 2) + nt * 8 + 2 * (l & 3);
                float v0 = acc[mt][nt][2 * half + 0];
                float v1 = acc[mt][nt][2 * half + 1];
                float* cp = C + (size_t)gm * ldc + gn;
                if (EPI == EPI_GELU_POS) {
                    v0 += bias[gn];
                    v1 += bias[gn + 1];
                    v0 = 0.5f * v0 * (1.f + erff(v0 * 0.70710678118654752f));
                    v1 = 0.5f * v1 * (1.f + erff(v1 * 0.70710678118654752f));
                    v0 += p0 * pos_w[gn]     + p1 * pos_w[DMODEL + gn]     + pos_b[gn];
                    v1 += p0 * pos_w[gn + 1] + p1 * pos_w[DMODEL + gn + 1] + pos_b[gn + 1];
                } else if (EPI == EPI_ADD) {
                    float2 old = *reinterpret_cast<const float2*>(cp);
                    v0 += old.x;
                    v1 += old.y;
                }
                *reinterpret_cast<float2*>(cp) = make_float2(v0, v1);
            }
        }
    }
}

// =========================================================================
// TF32 tensor-core GEMM. Block 128x64, m16n8k8.
// SPLIT>0: K split over gridDim.z, partials -> C + z*M*N, no epilogue.
//          B columns >= Nreal read as 0 (clamped pointer, predicated).
// REDA=1:  A is SPLITK-sliced partials (g_part, lda=128); A-load sums slices.
// =========================================================================
__device__ __forceinline__ uint32_t f2tf(float f) {
    uint32_t u;
    asm("cvt.rna.tf32.f32 %0, %1;" : "=r"(u) : "f"(f));
    return u;
}

__device__ __forceinline__ void mma_tf32(float* d,
                                         uint32_t a0, uint32_t a1, uint32_t a2, uint32_t a3,
                                         uint32_t b0, uint32_t b1)
{
    asm volatile(
        "mma.sync.aligned.m16n8k8.row.col.f32.tf32.tf32.f32 "
        "{%0,%1,%2,%3},{%4,%5,%6,%7},{%8,%9},{%0,%1,%2,%3};"
        : "+f"(d[0]), "+f"(d[1]), "+f"(d[2]), "+f"(d[3])
        : "r"(a0), "r"(a1), "r"(a2), "r"(a3), "r"(b0), "r"(b1));
}

#define RSA 28
#define RSB 28

template <int EPI, int SPLIT, int REDA>
__global__ __launch_bounds__(256)
void gemm_tc(int M, int N, int K, int Nreal,
             const float* __restrict__ A, int lda,
             const float* __restrict__ B, int ldb,
             float* __restrict__ C, int ldc,
             const float* __restrict__ bias)
{
    __shared__ __align__(16) uint32_t sA[2][128 * RSA];
    __shared__ __align__(16) uint32_t sB[2][64 * RSB];

    const int t   = threadIdx.x;
    const int l   = t & 31;
    const int wid = t >> 5;
    const int wm  = wid >> 1;
    const int wn  = wid & 1;
    const int bm  = blockIdx.y << 7;
    const int bn  = blockIdx.x << 6;

    int kOff = 0, KS = K;
    if (SPLIT > 0) {
        KS   = K / SPLIT;
        kOff = blockIdx.z * KS;
        C   += (size_t)blockIdx.z * M * N;
    }

    const int am = t >> 1;
    const int ah = t & 1;
    const float* Asrc = A + (size_t)(bm + am) * lda + kOff + ah * 8;
    const int bkq = t >> 6;
    const int bn0 = t & 63;
    const bool bok = (bn + bn0) < Nreal;
    const int bcol = bok ? (bn + bn0) : 0;
    const float* Bsrc = B + (size_t)(kOff + bkq) * ldb + bcol;

    float acc[2][4][4];
#pragma unroll
    for (int i = 0; i < 2; i++)
#pragma unroll
        for (int j = 0; j < 4; j++)
#pragma unroll
            for (int k = 0; k < 4; k++) acc[i][j][k] = 0.f;

    float4 va0, va1;
    float  vb0, vb1, vb2, vb3;

    auto loadA = [&](int k0) {
        va0 = *reinterpret_cast<const float4*>(Asrc + k0);
        va1 = *reinterpret_cast<const float4*>(Asrc + k0 + 4);
        if (REDA) {
#pragma unroll
            for (int z = 1; z < SPLITK; z++) {
                const float* s = Asrc + (size_t)z * L_TOK * 128 + k0;
                float4 e0 = *reinterpret_cast<const float4*>(s);
                float4 e1 = *reinterpret_cast<const float4*>(s + 4);
                va0.x += e0.x; va0.y += e0.y; va0.z += e0.z; va0.w += e0.w;
                va1.x += e1.x; va1.y += e1.y; va1.z += e1.z; va1.w += e1.w;
            }
        }
    };
    auto loadB = [&](int k0) {
        if (bok) {
            const float* bs = Bsrc + (size_t)k0 * ldb;
            vb0 = bs[0];
            vb1 = bs[(size_t)4 * ldb];
            vb2 = bs[(size_t)8 * ldb];
            vb3 = bs[(size_t)12 * ldb];
        } else {
            vb0 = vb1 = vb2 = vb3 = 0.f;
        }
    };
    auto storeAB = [&](int nb) {
        uint4 w0 = make_uint4(f2tf(va0.x), f2tf(va1.x), f2tf(va0.y), f2tf(va1.y));
        uint4 w1 = make_uint4(f2tf(va0.z), f2tf(va1.z), f2tf(va0.w), f2tf(va1.w));
        *reinterpret_cast<uint4*>(&sA[nb][am * RSA + ah * 8])     = w0;
        *reinterpret_cast<uint4*>(&sA[nb][am * RSA + ah * 8 + 4]) = w1;
        *reinterpret_cast<uint2*>(&sB[nb][bn0 * RSB + 2 * bkq])     = make_uint2(f2tf(vb0), f2tf(vb1));
        *reinterpret_cast<uint2*>(&sB[nb][bn0 * RSB + 8 + 2 * bkq]) = make_uint2(f2tf(vb2), f2tf(vb3));
    };

    loadA(0);
    loadB(0);
    storeAB(0);
    __syncthreads();

    const int NT = KS >> 4;
    for (int kt = 0; kt < NT; kt++) {
        if (kt + 1 < NT) {
            const int k0 = (kt + 1) << 4;
            loadA(k0);
            loadB(k0);
        }
        const int buf = kt & 1;
#pragma unroll
        for (int ks = 0; ks < 2; ks++) {
            uint32_t af[2][4];
#pragma unroll
            for (int mt = 0; mt < 2; mt++) {
                const int r = wm * 32 + mt * 16 + (l >> 2);
                uint2 lo = *reinterpret_cast<const uint2*>(&sA[buf][r * RSA + ks * 8 + 2 * (l & 3)]);
                uint2 hi = *reinterpret_cast<const uint2*>(&sA[buf][(r + 8) * RSA + ks * 8 + 2 * (l & 3)]);
                af[mt][0] = lo.x; af[mt][1] = hi.x; af[mt][2] = lo.y; af[mt][3] = hi.y;
            }
#pragma unroll
            for (int nt = 0; nt < 4; nt++) {
                const int n = wn * 32 + nt * 8 + (l >> 2);
                uint2 bf = *reinterpret_cast<const uint2*>(&sB[buf][n * RSB + ks * 8 + 2 * (l & 3)]);
#pragma unroll
                for (int mt = 0; mt < 2; mt++)
                    mma_tf32(acc[mt][nt],
                             af[mt][0], af[mt][1], af[mt][2], af[mt][3], bf.x, bf.y);
            }
        }
        if (kt + 1 < NT) {
            storeAB((kt + 1) & 1);
        }
        __syncthreads();
    }

#pragma unroll
    for (int mt = 0; mt < 2; mt++) {
#pragma unroll
        for (int half = 0; half < 2; half++) {
            const int gm = bm + wm * 32 + mt * 16 + (l >> 2) + half * 8;
#pragma unroll
            for (int nt = 0; nt < 4; nt++) {
                const int gn = bn + wn * 32 + nt * 8 + 2 * (l & 3);
                float v0 = acc[mt][nt][2 * half + 0];
                float v1 = acc[mt][nt][2 * half + 1];
                float* cp = C + (size_t)gm * ldc + gn;
                if (EPI == EPI_SOFTPLUS) {
                    v0 += bias[gn];
                    v1 += bias[gn + 1];
                    v0 = (v0 > 15.f) ? v0 : log1pf(expf(v0));
                    v1 = (v1 > 15.f) ? v1 : log1pf(expf(v1));
                }
                *reinterpret_cast<float2*>(cp) = make_float2(v0, v1);
            }
        }
    }
}

// ---------------- attn reduce: sum slices, tanh*w2, row-sum -> scores ------
__global__ __launch_bounds__(128)
void attn_score_kernel(const float* __restrict__ part,
                       const float* __restrict__ b1,
                       const float* __restrict__ w2,
                       const float* __restrict__ b2,
                       float* __restrict__ scores)
{
    __shared__ float red[128];
    int row = blockIdx.x;
    int d   = threadIdx.x;
    size_t off = (size_t)row * 128 + d;
    float v = part[off];
#pragma unroll
    for (int z = 1; z < SPLITK; z++)
        v += part[(size_t)z * L_TOK * 128 + off];
    float s = tanhf(v + b1[d]) * w2[d];
    red[d] = s;
    __syncthreads();
    for (int st = 64; st > 0; st >>= 1) {
        if (d < st) red[d] += red[d + st];
        __syncthreads();
    }
    if (d == 0) scores[row] = red[0] + b2[0];
}

// ---------------- per-row RMS scale ----------------
__global__ __launch_bounds__(256)
void rownorm_kernel(const float* __restrict__ h, float* __restrict__ rn)
{
    int w = threadIdx.x >> 5;
    int l = threadIdx.x & 31;
    int row = blockIdx.x * 8 + w;
    const float* r = h + (size_t)row * DMODEL;
    float ss = 0.f;
#pragma unroll
    for (int i = 0; i < DMODEL / 32; i++) {
        float v = r[l + i * 32];
        ss = fmaf(v, v, ss);
    }
#pragma unroll
    for (int o = 16; o > 0; o >>= 1) ss += __shfl_down_sync(0xffffffff, ss, o);
    if (l == 0) rn[row] = rsqrtf(ss * (1.f / DMODEL) + 1e-5f);
}

// ---------------- block reduce helper ----------------
__device__ __forceinline__ float block_reduce_sum(float v, float* sred)
{
    int tid = threadIdx.x;
#pragma unroll
    for (int o = 16; o > 0; o >>= 1) v += __shfl_down_sync(0xffffffff, v, o);
    if ((tid & 31) == 0) sred[tid >> 5] = v;
    __syncthreads();
    float r;
    if (tid < 32) {
        int nw = blockDim.x >> 5;
        r = (tid < nw) ? sred[tid] : 0.f;
#pragma unroll
        for (int o = 16; o > 0; o >>= 1) r += __shfl_down_sync(0xffffffff, r, o);
        if (tid == 0) sred[0] = r;
    }
    __syncthreads();
    r = sred[0];
    __syncthreads();
    return r;
}

// ---------------- LayerNorm ----------------
__global__ void layernorm_kernel(const float* __restrict__ h,
                                 const float* __restrict__ w,
                                 const float* __restrict__ b,
                                 float* __restrict__ out)
{
    __shared__ float sred[32];
    int t = blockIdx.x;
    const float* row = h + (size_t)t * DMODEL;
    float s = 0.f, ss = 0.f;
    for (int d = threadIdx.x; d < DMODEL; d += blockDim.x) {
        float v = row[d];
        s += v;
        ss = fmaf(v, v, ss);
    }
    float tot  = block_reduce_sum(s, sred);
    float tot2 = block_reduce_sum(ss, sred);
    float mu  = tot * (1.f / DMODEL);
    float var = tot2 * (1.f / DMODEL) - mu * mu;
    float sc  = rsqrtf(var + 1e-5f);
    for (int d = threadIdx.x; d < DMODEL; d += blockDim.x)
        out[(size_t)t * DMODEL + d] = (row[d] - mu) * sc * w[d] + b[d];
}

// ---------------- depthwise causal conv1d + SiLU ----------------
__global__ void conv_silu_kernel(const float* __restrict__ xz,
                                 const float* __restrict__ cw,
                                 const float* __restrict__ cb,
                                 float* __restrict__ u)
{
    int idx = blockIdx.x * blockDim.x + threadIdx.x;
    if (idx >= L_TOK * DINNER) return;
    int t = idx >> 10, c = idx & 1023;
    const float* w = cw + c * 4;
    float acc = cb[c];
#pragma unroll
    for (int k = 0; k < 4; k++) {
        int tt = t - 3 + k;
        if (tt >= 0) acc = fmaf(w[k], xz[(size_t)tt * (2 * DINNER) + c], acc);
    }
    u[idx] = acc / (1.f + __expf(-acc));
}

// ---------------- scan pass A (B staged from split-K partials) ------------
__global__ __launch_bounds__(128)
void scan_a_kernel(const float* __restrict__ delta,
                   const float* __restrict__ u,
                   const float* __restrict__ part,
                   const float* __restrict__ A_log,
                   float* __restrict__ Pout,
                   float* __restrict__ Sout)
{
    __shared__ float sB[CHUNK][DSTATE];
    int e  = blockIdx.y * 128 + threadIdx.x;
    int c  = blockIdx.x;
    int t0 = c * CHUNK;
    for (int i = threadIdx.x; i < CHUNK * DSTATE; i += 128) {
        int tl = i >> 4, n = i & 15;
        size_t off = (size_t)(t0 + tl) * 128 + 32 + n;
        float s = part[off];
#pragma unroll
        for (int z = 1; z < SPLITK; z++)
            s += part[(size_t)z * L_TOK * 128 + off];
        sB[tl][n] = s;
    }
    __syncthreads();
    float Aneg[DSTATE], h[DSTATE];
    bool fast = true;
#pragma unroll
    for (int n = 0; n < DSTATE; n++) {
        Aneg[n] = -expf(A_log[(size_t)e * DSTATE + n]);
        fast = fast && (fabsf(Aneg[n] + (float)(n + 1)) < 1e-3f * (n + 1));
        h[n] = 0.f;
    }
    size_t base = ((size_t)c * DINNER + e) * DSTATE;
    if (fast) {
        float sumdl = 0.f;
        for (int tl = 0; tl < CHUNK; tl++) {
            int   t  = t0 + tl;
            float dl = delta[(size_t)t * DINNER + e];
            float ul = u[(size_t)t * DINNER + e];
            float du = dl * ul;
            float E  = __expf(-dl);
            sumdl += dl;
            float pw = 1.f;
#pragma unroll
            for (int n = 0; n < DSTATE; n++) {
                pw *= E;
                h[n] = fmaf(pw, h[n], du * sB[tl][n]);
            }
        }
        float Es = __expf(-sumdl);
        float pp = 1.f;
#pragma unroll
        for (int n = 0; n < DSTATE; n++) {
            pp *= Es;
            Sout[base + n] = h[n];
            Pout[base + n] = pp;
        }
    } else {
        float P[DSTATE];
#pragma unroll
        for (int n = 0; n < DSTATE; n++) P[n] = 1.f;
        for (int tl = 0; tl < CHUNK; tl++) {
            int   t  = t0 + tl;
            float dl = delta[(size_t)t * DINNER + e];
            float ul = u[(size_t)t * DINNER + e];
            float du = dl * ul;
#pragma unroll
            for (int n = 0; n < DSTATE; n++) {
                float dA = __expf(dl * Aneg[n]);
                h[n] = fmaf(dA, h[n], du * sB[tl][n]);
                P[n] *= dA;
            }
        }
#pragma unroll
        for (int n = 0; n < DSTATE; n++) {
            Sout[base + n] = h[n];
            Pout[base + n] = P[n];
        }
    }
}

// ---------------- scan pass B ----------------
__global__ void scan_b_kernel(const float* __restrict__ P,
                              const float* __restrict__ S,
                              float* __restrict__ init)
{
    int e = blockIdx.x * blockDim.x + threadIdx.x;
    if (e >= DINNER) return;
    float h[DSTATE];
#pragma unroll
    for (int n = 0; n < DSTATE; n++) h[n] = 0.f;
    for (int c = 0; c < NCHUNK; c++) {
        size_t base = ((size_t)c * DINNER + e) * DSTATE;
#pragma unroll
        for (int n = 0; n < DSTATE; n++) init[base + n] = h[n];
#pragma unroll
        for (int n = 0; n < DSTATE; n++)
            h[n] = fmaf(P[base + n], h[n], S[base + n]);
    }
}

// ---------------- scan pass C (B/C staged from split-K partials) -----------
__global__ __launch_bounds__(128)
void scan_c_kernel(const float* __restrict__ delta,
                   const float* __restrict__ u,
                   const float* __restrict__ part,
                   const float* __restrict__ A_log,
                   const float* __restrict__ Dd,
                   const float* __restrict__ init,
                   const float* __restrict__ xz,
                   float* __restrict__ y)
{
    __shared__ float sB[CHUNK][DSTATE];
    __shared__ float sC[CHUNK][DSTATE];
    int e  = blockIdx.y * 128 + threadIdx.x;
    int c  = blockIdx.x;
    int t0 = c * CHUNK;
    for (int i = threadIdx.x; i < CHUNK * DSTATE; i += 128) {
        int tl = i >> 4, n = i & 15;
        size_t offB = (size_t)(t0 + tl) * 128 + 32 + n;
        size_t offC = (size_t)(t0 + tl) * 128 + 48 + n;
        float sb = part[offB];
        float sc2 = part[offC];
#pragma unroll
        for (int z = 1; z < SPLITK; z++) {
            sb  += part[(size_t)z * L_TOK * 128 + offB];
            sc2 += part[(size_t)z * L_TOK * 128 + offC];
        }
        sB[tl][n] = sb;
        sC[tl][n] = sc2;
    }
    __syncthreads();
    float Aneg[DSTATE], h[DSTATE];
    bool fast = true;
    size_t base = ((size_t)c * DINNER + e) * DSTATE;
#pragma unroll
    for (int n = 0; n < DSTATE; n++) {
        Aneg[n] = -expf(A_log[(size_t)e * DSTATE + n]);
        fast = fast && (fabsf(Aneg[n] + (float)(n + 1)) < 1e-3f * (n + 1));
        h[n]    = init[base + n];
    }
    float Dde = Dd[e];
    if (fast) {
        for (int tl = 0; tl < CHUNK; tl++) {
            int   t  = t0 + tl;
            float dl = delta[(size_t)t * DINNER + e];
            float ul = u[(size_t)t * DINNER + e];
            float du = dl * ul;
            float acc = Dde * ul;
            float E  = __expf(-dl);
            float pw = 1.f;
#pragma unroll
            for (int n = 0; n < DSTATE; n++) {
                pw *= E;
                h[n] = fmaf(pw, h[n], du * sB[tl][n]);
                acc  = fmaf(h[n], sC[tl][n], acc);
            }
            float zv = xz[(size_t)t * (2 * DINNER) + DINNER + e];
            float sz = zv / (1.f + __expf(-zv));
            y[(size_t)t * DINNER + e] = acc * sz;
        }
    } else {
        for (int tl = 0; tl < CHUNK; tl++) {
            int   t  = t0 + tl;
            float dl = delta[(size_t)t * DINNER + e];
            float ul = u[(size_t)t * DINNER + e];
            float du = dl * ul;
            float acc = Dde * ul;
#pragma unroll
            for (int n = 0; n < DSTATE; n++) {
                float dA = __expf(dl * Aneg[n]);
                h[n] = fmaf(dA, h[n], du * sB[tl][n]);
                acc  = fmaf(h[n], sC[tl][n], acc);
            }
            float zv = xz[(size_t)t * (2 * DINNER) + DINNER + e];
            float sz = zv / (1.f + __expf(-zv));
            y[(size_t)t * DINNER + e] = acc * sz;
        }
    }
}

// ---------------- softmax stats ----------------
__global__ __launch_bounds__(512)
void softmax_stats_kernel(const float* __restrict__ scores,
                          float* __restrict__ stats)
{
    __shared__ float red[512];
    int tid = threadIdx.x;
    float mx = fmaxf(scores[tid], scores[tid + 512]);
    mx = fmaxf(mx, fmaxf(scores[tid + 1024], scores[tid + 1536]));
    red[tid] = mx;
    __syncthreads();
    for (int s = 256; s > 0; s >>= 1) {
        if (tid < s) red[tid] = fmaxf(red[tid], red[tid + s]);
        __syncthreads();
    }
    mx = red[0];
    __syncthreads();
    float lsum = expf(scores[tid] - mx) + expf(scores[tid + 512] - mx)
               + expf(scores[tid + 1024] - mx) + expf(scores[tid + 1536] - mx);
    red[tid] = lsum;
    __syncthreads();
    for (int s = 256; s > 0; s >>= 1) {
        if (tid < s) red[tid] += red[tid + s];
        __syncthreads();
    }
    if (tid == 0) { stats[0] = mx; stats[1] = red[0]; }
}

// ---------------- pooling partials ----------------
__global__ __launch_bounds__(512)
void pool_partial_kernel(const float* __restrict__ hn,
                         const float* __restrict__ scores,
                         const float* __restrict__ stats,
                         float* __restrict__ pool)
{
    int tid = threadIdx.x;
    int b   = blockIdx.x;
    float mx = stats[0];
    float acc = 0.f;
    int t0 = b * (L_TOK / NPOOL);
    for (int i = 0; i < L_TOK / NPOOL; i++) {
        int t = t0 + i;
        float w = __expf(scores[t] - mx);
        acc = fmaf(w, hn[(size_t)t * DMODEL + tid], acc);
    }
    pool[(size_t)b * DMODEL + tid] = acc;
}

// ---------------- final reduce + classifier ----------------
__global__ __launch_bounds__(512)
void pool_final_kernel(const float* __restrict__ pool,
                       const float* __restrict__ stats,
                       const float* __restrict__ cls_w,
                       const float* __restrict__ cls_b,
                       float* __restrict__ out)
{
    __shared__ float red[512];
    int tid = threadIdx.x;
    float acc = 0.f;
#pragma unroll
    for (int b = 0; b < NPOOL; b++)
        acc += pool[(size_t)b * DMODEL + tid];
    acc /= stats[1];
#pragma unroll
    for (int c = 0; c < 2; c++) {
        red[tid] = acc * cls_w[tid * 2 + c];
        __syncthreads();
        for (int s = 256; s > 0; s >>= 1) {
            if (tid < s) red[tid] += red[tid + s];
            __syncthreads();
        }
        if (tid == 0) out[c] = red[0] + cls_b[c];
        __syncthreads();
    }
}

// ---------------- host launcher ----------------
extern "C" void kernel_launch(void* const* d_in, const int* in_sizes, int n_in,
                              void* d_out, int out_size)
{
    const float* x       = (const float*)d_in[0];
    const float* pos     = (const float*)d_in[1];
    const float* fc1_w   = (const float*)d_in[2];
    const float* fc1_b   = (const float*)d_in[3];
    const float* pos_w   = (const float*)d_in[4];
    const float* pos_b   = (const float*)d_in[5];
    const float* in_proj = (const float*)d_in[6];
    const float* conv_w  = (const float*)d_in[7];
    const float* conv_b  = (const float*)d_in[8];
    const float* x_proj  = (const float*)d_in[9];
    const float* dt_w    = (const float*)d_in[10];
    const float* dt_b    = (const float*)d_in[11];
    const float* A_log   = (const float*)d_in[12];
    const float* Dd      = (const float*)d_in[13];
    const float* out_w   = (const float*)d_in[14];
    const float* rms_w   = (const float*)d_in[15];
    const float* norm_w  = (const float*)d_in[16];
    const float* norm_b  = (const float*)d_in[17];
    const float* attn_w1 = (const float*)d_in[18];
    const float* attn_b1 = (const float*)d_in[19];
    const float* attn_w2 = (const float*)d_in[20];
    const float* attn_b2 = (const float*)d_in[21];
    const float* cls_w   = (const float*)d_in[22];
    const float* cls_b   = (const float*)d_in[23];

    float *p_h, *p_hn, *p_xz, *p_u, *p_delta, *p_y;
    float *p_P, *p_S, *p_init, *p_scores, *p_rnorm, *p_stats, *p_pool, *p_part;
    cudaGetSymbolAddress((void**)&p_h,      g_h);
    cudaGetSymbolAddress((void**)&p_hn,     g_hn);
    cudaGetSymbolAddress((void**)&p_xz,     g_xz);
    cudaGetSymbolAddress((void**)&p_u,      g_u);
    cudaGetSymbolAddress((void**)&p_delta,  g_delta);
    cudaGetSymbolAddress((void**)&p_y,      g_y);
    cudaGetSymbolAddress((void**)&p_P,      g_P);
    cudaGetSymbolAddress((void**)&p_S,      g_S);
    cudaGetSymbolAddress((void**)&p_init,   g_init);
    cudaGetSymbolAddress((void**)&p_scores, g_scores);
    cudaGetSymbolAddress((void**)&p_rnorm,  g_rnorm);
    cudaGetSymbolAddress((void**)&p_stats,  g_stats);
    cudaGetSymbolAddress((void**)&p_pool,   g_pool);
    cudaGetSymbolAddress((void**)&p_part,   g_part);

    // fc1 + GELU + pos
    gemm_bf<EPI_GELU_POS, 64, 0><<<dim3(DMODEL / 64, L_TOK / 128), 256>>>(
        L_TOK, DMODEL, INDIM, x, INDIM, fc1_w, DMODEL, p_h, DMODEL,
        fc1_b, pos, pos_w, pos_b, nullptr, nullptr);

    for (int l = 0; l < NLAYER; l++) {
        // per-row RMS scales, fused into in_proj A-load
        rownorm_kernel<<<L_TOK / 8, 256>>>(p_h, p_rnorm);

        gemm_bf<EPI_NONE, 128, 1><<<dim3(2 * DINNER / 128, L_TOK / 128), 256>>>(
            L_TOK, 2 * DINNER, DMODEL,
            p_h, DMODEL,
            in_proj + (size_t)l * DMODEL * 2 * DINNER, 2 * DINNER,
            p_xz, 2 * DINNER, nullptr, nullptr, nullptr, nullptr,
            p_rnorm, rms_w + (size_t)l * DMODEL);

        conv_silu_kernel<<<(L_TOK * DINNER) / 256, 256>>>(
            p_xz, conv_w + (size_t)l * DINNER * 4, conv_b + (size_t)l * DINNER, p_u);

        // x_proj split-K tf32 straight from [1024,80] weights (predicated cols)
        gemm_tc<EPI_NONE, SPLITK, 0><<<dim3(2, L_TOK / 128, SPLITK), 256>>>(
            L_TOK, 128, DINNER, 80,
            p_u, DINNER,
            x_proj + (size_t)l * DINNER * 80, 80,
            p_part, 128, nullptr);

        // dt-proj tf32; A-load sums the split-K partial slices (cols 0..31)
        gemm_tc<EPI_SOFTPLUS, 0, 1><<<dim3(DINNER / 64, L_TOK / 128), 256>>>(
            L_TOK, DINNER, DTRANK, DINNER,
            p_part, 128,
            dt_w + (size_t)l * DTRANK * DINNER, DINNER,
            p_delta, DINNER, dt_b + (size_t)l * DINNER);

        scan_a_kernel<<<dim3(NCHUNK, DINNER / 128), 128>>>(
            p_delta, p_u, p_part, A_log + (size_t)l * DINNER * DSTATE, p_P, p_S);
        scan_b_kernel<<<DINNER / 256, 256>>>(p_P, p_S, p_init);
        scan_c_kernel<<<dim3(NCHUNK, DINNER / 128), 128>>>(
            p_delta, p_u, p_part, A_log + (size_t)l * DINNER * DSTATE,
            Dd + (size_t)l * DINNER, p_init, p_xz, p_y);

        gemm_bf<EPI_ADD, 64, 0><<<dim3(DMODEL / 64, L_TOK / 128), 256>>>(
            L_TOK, DMODEL, DINNER,
            p_y, DINNER,
            out_w + (size_t)l * DINNER * DMODEL, DMODEL,
            p_h, DMODEL, nullptr, nullptr, nullptr, nullptr, nullptr, nullptr);
    }

    layernorm_kernel<<<L_TOK, 256>>>(p_h, norm_w, norm_b, p_hn);

    gemm_tc<EPI_NONE, SPLITK, 0><<<dim3(2, L_TOK / 128, SPLITK), 256>>>(
        L_TOK, 128, DMODEL, 128,
        p_hn, DMODEL,
        attn_w1, 128,
        p_part, 128, nullptr);
    attn_score_kernel<<<L_TOK, 128>>>(p_part, attn_b1, attn_w2, attn_b2, p_scores);

    softmax_stats_kernel<<<1, 512>>>(p_scores, p_stats);
    pool_partial_kernel<<<NPOOL, 512>>>(p_hn, p_scores, p_stats, p_pool);
    pool_final_kernel<<<1, 512>>>(p_pool, p_stats, cls_w, cls_b, (float*)d_out);
}